// round 9
// baseline (speedup 1.0000x reference)
#include <cuda_runtime.h>

// HSE (hard-sigmoid squeeze-excitation) for x[64, 768, 28, 28] fp32.
// R8: software-pipelined chunked DAG. 8 chunks x 8 batches. Each launched
// kernel is a union of independent roles (scale chunk g-2 | mlp chunk g-1 |
// pool chunk g) mapped to disjoint block ranges; kernel boundaries give all
// ordering — no atomics, fences, flags, or spins (R7's failure modes).
// The scale re-read of x hits L2 (live window 58 MB < 126 MB), so DRAM
// traffic is 308 MB with read/write overlap.

#define BATCH    64
#define CH       768
#define HID      192
#define HW       784
#define PLANES   (BATCH * CH)       // 49152
#define VEC4     (HW / 4)           // 196 float4 per plane

#define NCHUNK   8
#define CB       (BATCH / NCHUNK)   // 8 batches per chunk
#define CPLANES  (CB * CH)          // 6144 planes per chunk

#define SCALE_BLKS 768              // 6144 warps, plane each
#define MLP_BLKS   CB               // block per batch
#define TRANS_BLKS 16
#define POOL_BLKS  384              // 3072 warps, 2 planes each
#define GRID (SCALE_BLKS + MLP_BLKS + TRANS_BLKS + POOL_BLKS)  // 1176

__device__ float g_pooled[PLANES];
__device__ float g_sc[PLANES];
__device__ float g_w2t[HID * CH];   // w2 transposed: [k][c], c contiguous

__global__ __launch_bounds__(256)
void step_kernel(const float4* __restrict__ x,
                 const float4* __restrict__ w1,
                 const float*  __restrict__ b1,
                 const float*  __restrict__ w2,
                 const float*  __restrict__ b2,
                 float4*       __restrict__ out,
                 int pool_chunk, int mlp_chunk, int scale_chunk, int do_trans) {
    const int blk  = blockIdx.x;
    const int t    = threadIdx.x;
    const int lane = t & 31;
    const int wid  = t >> 5;

    // ---------------- role: scale chunk (L2-hot re-read) ----------------
    if (blk < SCALE_BLKS) {
        if (scale_chunk < 0) return;
        int plane = scale_chunk * CPLANES + blk * 8 + wid;
        float sv = g_sc[plane];
        const float4* p = x   + (size_t)plane * VEC4;
        float4*       o = out + (size_t)plane * VEC4;
#pragma unroll
        for (int i = 0; i < 6; i++) {
            float4 v = __ldcs(&p[lane + 32 * i]);   // dead after read
            v.x *= sv; v.y *= sv; v.z *= sv; v.w *= sv;
            __stcs(&o[lane + 32 * i], v);
        }
        if (lane < 4) {
            float4 v = __ldcs(&p[192 + lane]);
            v.x *= sv; v.y *= sv; v.z *= sv; v.w *= sv;
            __stcs(&o[192 + lane], v);
        }
        return;
    }

    // ---------------- role: MLP, one batch per block ----------------
    if (blk < SCALE_BLKS + MLP_BLKS) {
        if (mlp_chunk < 0) return;
        const int b = mlp_chunk * CB + (blk - SCALE_BLKS);

        __shared__ __align__(16) float p_s[CH];
        __shared__ __align__(16) float h_s[HID];

        p_s[t]       = g_pooled[b * CH + t];
        p_s[t + 256] = g_pooled[b * CH + t + 256];
        p_s[t + 512] = g_pooled[b * CH + t + 512];
        __syncthreads();

        // phase 1: h = relu(w1 @ pooled + b1). Warp handles rows wid+8k,
        // 4 rows per pass (shared pooled loads, 24 loads in flight).
        const float4* pv = reinterpret_cast<const float4*>(p_s);
#pragma unroll
        for (int jj = 0; jj < 6; jj++) {
            int r0 = wid + 32 * jj;              // rows r0, r0+8, r0+16, r0+24
            const float4* wr0 = w1 + (size_t)(r0)      * (CH / 4);
            const float4* wr1 = w1 + (size_t)(r0 + 8)  * (CH / 4);
            const float4* wr2 = w1 + (size_t)(r0 + 16) * (CH / 4);
            const float4* wr3 = w1 + (size_t)(r0 + 24) * (CH / 4);
            float a0 = 0, a1 = 0, a2 = 0, a3 = 0;
#pragma unroll
            for (int i = 0; i < 6; i++) {
                float4 p  = pv[lane + 32 * i];
                float4 v0 = wr0[lane + 32 * i];
                float4 v1 = wr1[lane + 32 * i];
                float4 v2 = wr2[lane + 32 * i];
                float4 v3 = wr3[lane + 32 * i];
                a0 += v0.x * p.x + v0.y * p.y + v0.z * p.z + v0.w * p.w;
                a1 += v1.x * p.x + v1.y * p.y + v1.z * p.z + v1.w * p.w;
                a2 += v2.x * p.x + v2.y * p.y + v2.z * p.z + v2.w * p.w;
                a3 += v3.x * p.x + v3.y * p.y + v3.z * p.z + v3.w * p.w;
            }
#pragma unroll
            for (int off = 16; off; off >>= 1) {
                a0 += __shfl_xor_sync(0xffffffffu, a0, off);
                a1 += __shfl_xor_sync(0xffffffffu, a1, off);
                a2 += __shfl_xor_sync(0xffffffffu, a2, off);
                a3 += __shfl_xor_sync(0xffffffffu, a3, off);
            }
            if (lane == 0) {
                h_s[r0]      = fmaxf(a0 + b1[r0],      0.0f);
                h_s[r0 + 8]  = fmaxf(a1 + b1[r0 + 8],  0.0f);
                h_s[r0 + 16] = fmaxf(a2 + b1[r0 + 16], 0.0f);
                h_s[r0 + 24] = fmaxf(a3 + b1[r0 + 24], 0.0f);
            }
        }
        __syncthreads();

        // phase 2: s = hardsigmoid(w2 @ h + b2) via transposed w2t —
        // thread-per-output, coalesced: thread t owns c = t, t+256, t+512.
        float a0 = 0, a1 = 0, a2 = 0;
#pragma unroll 4
        for (int k = 0; k < HID; k++) {
            float hk = h_s[k];
            const float* row = g_w2t + k * CH;
            a0 += row[t]       * hk;
            a1 += row[t + 256] * hk;
            a2 += row[t + 512] * hk;
        }
        g_sc[b * CH + t]       = __saturatef(fmaf(a0 + b2[t],       1.0f / 6.0f, 0.5f));
        g_sc[b * CH + t + 256] = __saturatef(fmaf(a1 + b2[t + 256], 1.0f / 6.0f, 0.5f));
        g_sc[b * CH + t + 512] = __saturatef(fmaf(a2 + b2[t + 512], 1.0f / 6.0f, 0.5f));
        return;
    }

    // ---------------- role: transpose w2 [CH,HID] -> w2t [HID,CH] --------
    if (blk < SCALE_BLKS + MLP_BLKS + TRANS_BLKS) {
        if (!do_trans) return;
        int base = (blk - SCALE_BLKS - MLP_BLKS) * 256 + t;
        for (int idx = base; idx < CH * HID; idx += TRANS_BLKS * 256) {
            int c = idx / HID;
            int k = idx - c * HID;
            g_w2t[k * CH + c] = w2[idx];     // coalesced read
        }
        return;
    }

    // ---------------- role: pool chunk (2 planes per warp) ----------------
    {
        if (pool_chunk < 0) return;
        int w = (blk - SCALE_BLKS - MLP_BLKS - TRANS_BLKS) * 8 + wid;  // 0..3071
        int plane = pool_chunk * CPLANES + 2 * w;
        const float4* p0 = x + (size_t)plane * VEC4;
        const float4* p1 = p0 + VEC4;
        float s0 = 0.0f, s1 = 0.0f;
#pragma unroll
        for (int i = 0; i < 6; i++) {
            float4 a = p0[lane + 32 * i];
            float4 b = p1[lane + 32 * i];
            s0 += (a.x + a.y) + (a.z + a.w);
            s1 += (b.x + b.y) + (b.z + b.w);
        }
        if (lane < 4) {
            float4 a = p0[192 + lane];
            float4 b = p1[192 + lane];
            s0 += (a.x + a.y) + (a.z + a.w);
            s1 += (b.x + b.y) + (b.z + b.w);
        }
#pragma unroll
        for (int off = 16; off; off >>= 1) {
            s0 += __shfl_xor_sync(0xffffffffu, s0, off);
            s1 += __shfl_xor_sync(0xffffffffu, s1, off);
        }
        if (lane == 0) {
            g_pooled[plane]     = s0 * (1.0f / 784.0f);
            g_pooled[plane + 1] = s1 * (1.0f / 784.0f);
        }
    }
}

// ---------------------------------------------------------------------------
extern "C" void kernel_launch(void* const* d_in, const int* in_sizes, int n_in,
                              void* d_out, int out_size) {
    const float4* x  = (const float4*)d_in[0];
    const float4* w1 = (const float4*)d_in[1];
    const float*  b1 = (const float*)d_in[2];
    const float*  w2 = (const float*)d_in[3];
    const float*  b2 = (const float*)d_in[4];
    float4* out = (float4*)d_out;

    // Pipeline: pool(g) | mlp(g-1) | scale(g-2), ordering via kernel bounds.
    step_kernel<<<GRID, 256>>>(x, w1, b1, w2, b2, out, 0, -1, -1, 1);
    step_kernel<<<GRID, 256>>>(x, w1, b1, w2, b2, out, 1,  0, -1, 0);
    for (int g = 2; g < NCHUNK; g++)
        step_kernel<<<GRID, 256>>>(x, w1, b1, w2, b2, out, g, g - 1, g - 2, 0);
    step_kernel<<<GRID, 256>>>(x, w1, b1, w2, b2, out, -1, NCHUNK - 1, NCHUNK - 2, 0);
    step_kernel<<<GRID, 256>>>(x, w1, b1, w2, b2, out, -1, -1, NCHUNK - 1, 0);
}

// round 10
// speedup vs baseline: 3.3196x; 3.3196x over previous
#include <cuda_runtime.h>

// HSE (hard-sigmoid squeeze-excitation) for x[64, 768, 28, 28] fp32.
// R9: back to the 3-pass shape (R7-best 89.9us) with:
//  - scale stores via __stwt (write-through, no L2 allocate) so the output
//    stream cannot evict x's pool-pass L2 residue; reverse plane order
//    harvests that residue for the re-read.
//  - mlp2 fused into the scale kernel (warp computes its own s while its
//    x loads are in flight) — one less launch, no g_sc round-trip.
//  - mlp1 as warp-per-(b,row): 12288 warps, fully latency-parallel.

#define BATCH   64
#define CH      768
#define HID     192
#define HW      784
#define PLANES  (BATCH * CH)   // 49152
#define VEC4    (HW / 4)       // 196 float4 per plane

__device__ float g_pooled[PLANES];
__device__ float g_h[BATCH * HID];

// ---------------------------------------------------------------------------
// Kernel 1: global average pool. Warp per TWO planes (12 loads in flight).
// Default cache policy: x streams through L2, leaving the ~126MB tail
// resident for the scale pass.
// ---------------------------------------------------------------------------
__global__ __launch_bounds__(256) void pool_kernel(const float4* __restrict__ x) {
    int w    = (blockIdx.x * blockDim.x + threadIdx.x) >> 5;
    int lane = threadIdx.x & 31;
    if (w >= PLANES / 2) return;

    const float4* p0 = x + (size_t)(2 * w) * VEC4;
    const float4* p1 = p0 + VEC4;
    float s0 = 0.0f, s1 = 0.0f;
#pragma unroll
    for (int i = 0; i < 6; i++) {
        float4 a = p0[lane + 32 * i];
        float4 b = p1[lane + 32 * i];
        s0 += (a.x + a.y) + (a.z + a.w);
        s1 += (b.x + b.y) + (b.z + b.w);
    }
    if (lane < 4) {
        float4 a = p0[192 + lane];
        float4 b = p1[192 + lane];
        s0 += (a.x + a.y) + (a.z + a.w);
        s1 += (b.x + b.y) + (b.z + b.w);
    }
#pragma unroll
    for (int off = 16; off; off >>= 1) {
        s0 += __shfl_xor_sync(0xffffffffu, s0, off);
        s1 += __shfl_xor_sync(0xffffffffu, s1, off);
    }
    if (lane == 0) {
        g_pooled[2 * w]     = s0 * (1.0f / 784.0f);
        g_pooled[2 * w + 1] = s1 * (1.0f / 784.0f);
    }
}

// ---------------------------------------------------------------------------
// Kernel 2: h = relu(w1 @ pooled + b1). Warp per (b, row): 12288 warps.
// Both w1 row and pooled row loads are coalesced float4; pooled comes from
// L2 (48 KB total, re-read 192x per batch).
// ---------------------------------------------------------------------------
__global__ __launch_bounds__(256) void mlp1_kernel(const float4* __restrict__ w1,
                                                   const float*  __restrict__ b1) {
    int gw   = (blockIdx.x * blockDim.x + threadIdx.x) >> 5;   // 0..12287
    int lane = threadIdx.x & 31;
    if (gw >= BATCH * HID) return;
    int b = gw / HID;
    int r = gw - b * HID;

    const float4* pv   = reinterpret_cast<const float4*>(g_pooled) + b * (CH / 4);
    const float4* wrow = w1 + (size_t)r * (CH / 4);
    float acc = 0.0f;
#pragma unroll
    for (int i = 0; i < 6; i++) {
        float4 wv = wrow[lane + 32 * i];
        float4 p  = pv[lane + 32 * i];
        acc += wv.x * p.x + wv.y * p.y + wv.z * p.z + wv.w * p.w;
    }
#pragma unroll
    for (int off = 16; off; off >>= 1)
        acc += __shfl_xor_sync(0xffffffffu, acc, off);
    if (lane == 0) g_h[b * HID + r] = fmaxf(acc + b1[r], 0.0f);
}

// ---------------------------------------------------------------------------
// Kernel 3: fused s-compute + scale. Warp per plane, REVERSE order.
// x loads issue first; while they're in flight the warp computes
// s = hardsigmoid(dot(w2[c], h[b]) + b2[c]) from L2-resident w2/g_h.
// Stores are write-through (__stwt): no L2 allocation, so x's residue
// from the pool pass survives for the re-read.
// ---------------------------------------------------------------------------
__global__ __launch_bounds__(256) void scale_kernel(const float4* __restrict__ x,
                                                    const float2* __restrict__ w2,
                                                    const float*  __restrict__ b2,
                                                    float4* __restrict__ out) {
    int w    = (blockIdx.x * blockDim.x + threadIdx.x) >> 5;
    int lane = threadIdx.x & 31;
    if (w >= PLANES) return;

    int plane = PLANES - 1 - w;   // reverse: most-recently-pooled first
    int b = plane / CH;
    int c = plane - b * CH;

    const float4* p = x + (size_t)plane * VEC4;

    // issue the x loads first (independent of the dot)
    float4 v[6];
#pragma unroll
    for (int i = 0; i < 6; i++) v[i] = __ldcs(&p[lane + 32 * i]);
    float4 vt;
    bool tail = lane < 4;
    if (tail) vt = __ldcs(&p[192 + lane]);

    // compute this plane's scale while loads are in flight
    const float2* wrow = w2 + (size_t)c * (HID / 2);
    const float2* hv   = reinterpret_cast<const float2*>(g_h) + b * (HID / 2);
    float acc = 0.0f;
#pragma unroll
    for (int i = 0; i < 3; i++) {
        float2 wv = wrow[lane + 32 * i];
        float2 h  = hv[lane + 32 * i];
        acc += wv.x * h.x + wv.y * h.y;
    }
#pragma unroll
    for (int off = 16; off; off >>= 1)
        acc += __shfl_xor_sync(0xffffffffu, acc, off);
    float sv = __saturatef(fmaf(acc + b2[c], 1.0f / 6.0f, 0.5f));

    float4* o = out + (size_t)plane * VEC4;
#pragma unroll
    for (int i = 0; i < 6; i++) {
        v[i].x *= sv; v[i].y *= sv; v[i].z *= sv; v[i].w *= sv;
        __stwt(&o[lane + 32 * i], v[i]);
    }
    if (tail) {
        vt.x *= sv; vt.y *= sv; vt.z *= sv; vt.w *= sv;
        __stwt(&o[192 + lane], vt);
    }
}

// ---------------------------------------------------------------------------
extern "C" void kernel_launch(void* const* d_in, const int* in_sizes, int n_in,
                              void* d_out, int out_size) {
    const float4* x  = (const float4*)d_in[0];
    const float4* w1 = (const float4*)d_in[1];
    const float*  b1 = (const float*)d_in[2];
    const float2* w2 = (const float2*)d_in[3];
    const float*  b2 = (const float*)d_in[4];
    float4* out = (float4*)d_out;

    pool_kernel<<<PLANES / 2 / 8, 256>>>(x);               // 3072 blocks
    mlp1_kernel<<<BATCH * HID / 8, 256>>>(w1, b1);         // 1536 blocks
    scale_kernel<<<PLANES / 8, 256>>>(x, w2, b2, out);     // 6144 blocks
}